// round 17
// baseline (speedup 1.0000x reference)
#include <cuda_runtime.h>
#include <cuda_bf16.h>
#include <cstdint>

// ---------------- problem constants ----------------
#define BATCH 2
#define SEQ   2048
#define EMB   1024
#define HEADS 16
#define DK    64
#define MTOK  (BATCH * SEQ)            // 4096
#define ZBH   (BATCH * HEADS)          // 32
#define PLANE ((size_t)MTOK * EMB)     // elements per hi/lo plane

// ---------------- device scratch ----------------
__device__ __align__(16) __nv_bfloat16 g_x_hi [PLANE];
__device__ __align__(16) __nv_bfloat16 g_x_lo [PLANE];
__device__ __align__(16) __nv_bfloat16 g_w_hi [4][(size_t)EMB * EMB];   // wq,wk,wv,wo
__device__ __align__(16) __nv_bfloat16 g_w_lo [4][(size_t)EMB * EMB];
__device__ __align__(16) __nv_bfloat16 g_q    [2 * PLANE];              // hi | lo
__device__ __align__(16) __nv_bfloat16 g_k    [2 * PLANE];              // hi | lo
__device__ __align__(16) __nv_bfloat16 g_v    [2 * PLANE];              // hi | lo, [tok][emb]
__device__ __align__(16) __nv_bfloat16 g_at_hi[PLANE];
__device__ __align__(16) __nv_bfloat16 g_at_lo[PLANE];
__device__ __align__(16) unsigned char g_mask[BATCH * SEQ];

// ---------------- base-ISA PTX helpers ----------------
__device__ __forceinline__ uint32_t s2u(const void* p) {
    uint32_t a;
    asm("{ .reg .u64 t; cvta.to.shared.u64 t, %1; cvt.u32.u64 %0, t; }" : "=r"(a) : "l"(p));
    return a;
}
__device__ __forceinline__ void cpa16(uint32_t s, const void* g) {
    asm volatile("cp.async.cg.shared.global [%0], [%1], 16;" :: "r"(s), "l"(g));
}
#define CP_COMMIT() asm volatile("cp.async.commit_group;" ::: "memory")
#define CP_WAIT1()  asm volatile("cp.async.wait_group 1;"  ::: "memory")
#define CP_WAIT0()  asm volatile("cp.async.wait_group 0;"  ::: "memory")

__device__ __forceinline__ void ldsm4(uint32_t a, uint32_t r[4]) {
    asm volatile("ldmatrix.sync.aligned.m8n8.x4.shared.b16 {%0,%1,%2,%3}, [%4];"
        : "=r"(r[0]), "=r"(r[1]), "=r"(r[2]), "=r"(r[3]) : "r"(a));
}
__device__ __forceinline__ void ldsm4t(uint32_t a, uint32_t r[4]) {
    asm volatile("ldmatrix.sync.aligned.m8n8.x4.trans.shared.b16 {%0,%1,%2,%3}, [%4];"
        : "=r"(r[0]), "=r"(r[1]), "=r"(r[2]), "=r"(r[3]) : "r"(a));
}
__device__ __forceinline__ void mma16816(float c[4], const uint32_t a[4], uint32_t b0, uint32_t b1) {
    asm volatile(
        "mma.sync.aligned.m16n8k16.row.col.f32.bf16.bf16.f32 "
        "{%0,%1,%2,%3}, {%4,%5,%6,%7}, {%8,%9}, {%0,%1,%2,%3};"
        : "+f"(c[0]), "+f"(c[1]), "+f"(c[2]), "+f"(c[3])
        : "r"(a[0]), "r"(a[1]), "r"(a[2]), "r"(a[3]), "r"(b0), "r"(b1));
}
__device__ __forceinline__ void split2(float a, float b, uint32_t& hi, uint32_t& lo) {
    __nv_bfloat16 ha = __float2bfloat16(a), hb = __float2bfloat16(b);
    __nv_bfloat16 la = __float2bfloat16(a - __bfloat162float(ha));
    __nv_bfloat16 lb = __float2bfloat16(b - __bfloat162float(hb));
    __nv_bfloat162 hv; hv.x = ha; hv.y = hb;
    __nv_bfloat162 lv; lv.x = la; lv.y = lb;
    hi = *(uint32_t*)&hv; lo = *(uint32_t*)&lv;
}

// ---------------- mask canonicalization ----------------
__global__ void mask_canon_kernel(const void* __restrict__ raw) {
    __shared__ int sInt, sFloat;
    int t = threadIdx.x;
    if (t == 0) { sInt = 1; sFloat = 1; }
    __syncthreads();
    const unsigned int* w = (const unsigned int*)raw;
    int okInt = 1, okFloat = 1;
    for (int i = t; i < (BATCH * SEQ) / 4; i += 256) {
        unsigned int v = w[i];
        if (v > 1u) okInt = 0;
        if (v != 0u && v != 0x3F800000u) okFloat = 0;
    }
    if (!okInt)   atomicAnd(&sInt, 0);
    if (!okFloat) atomicAnd(&sFloat, 0);
    __syncthreads();
    if (sInt) {
        const int* ip = (const int*)raw;
        for (int i = t; i < BATCH * SEQ; i += 256) g_mask[i] = (unsigned char)(ip[i] != 0);
    } else if (sFloat) {
        const float* fp = (const float*)raw;
        for (int i = t; i < BATCH * SEQ; i += 256) g_mask[i] = (unsigned char)(fp[i] != 0.0f);
    } else {
        const unsigned char* cp = (const unsigned char*)raw;
        for (int i = t; i < BATCH * SEQ; i += 256) g_mask[i] = (unsigned char)(cp[i] != 0);
    }
}

// ---------------- fp32 -> bf16 hi/lo split (single array) ----------------
__global__ void __launch_bounds__(256) split_kernel(
    const float* __restrict__ in, __nv_bfloat16* __restrict__ h,
    __nv_bfloat16* __restrict__ l, int n4)
{
    int i = blockIdx.x * 256 + threadIdx.x;
    if (i >= n4) return;
    float4 v = ((const float4*)in)[i];
    float a[4] = { v.x, v.y, v.z, v.w };
    __nv_bfloat16 hv[4], lv[4];
    #pragma unroll
    for (int q = 0; q < 4; q++) {
        hv[q] = __float2bfloat16(a[q]);
        lv[q] = __float2bfloat16(a[q] - __bfloat162float(hv[q]));
    }
    ((uint2*)h)[i] = *(uint2*)hv;
    ((uint2*)l)[i] = *(uint2*)lv;
}

// ---------------- fused wq/wk/wv split (one launch) ----------------
__global__ void __launch_bounds__(256) split3_kernel(
    const float* __restrict__ a, const float* __restrict__ b,
    const float* __restrict__ c)
{
    const int wsel = blockIdx.x >> 10;            // 1024 blocks per weight
    const int i = (blockIdx.x & 1023) * 256 + threadIdx.x;   // < 262144
    const float* src = (wsel == 0) ? a : (wsel == 1) ? b : c;
    __nv_bfloat16* h = &g_w_hi[wsel][0];
    __nv_bfloat16* l = &g_w_lo[wsel][0];
    float4 v = ((const float4*)src)[i];
    float x[4] = { v.x, v.y, v.z, v.w };
    __nv_bfloat16 hv[4], lv[4];
    #pragma unroll
    for (int q = 0; q < 4; q++) {
        hv[q] = __float2bfloat16(x[q]);
        lv[q] = __float2bfloat16(x[q] - __bfloat162float(hv[q]));
    }
    ((uint2*)h)[i] = *(uint2*)hv;
    ((uint2*)l)[i] = *(uint2*)lv;
}

// ---------------- 128x128 HMMA split-bf16 GEMM, 2 CTAs/SM ----------------
// 8 warps (2M x 4N), warp tile 64x32, BK=32, double buffer, smem 81920.
// D = A B^T (NT), 3-split. EPIMODE 0: fp32 out. EPIMODE 3: QKV dispatch.
template<int EPIMODE>
__global__ void __launch_bounds__(256, 2)
mm128(const __nv_bfloat16* __restrict__ Ah, const __nv_bfloat16* __restrict__ Al,
      const __nv_bfloat16* __restrict__ Bh, const __nv_bfloat16* __restrict__ Bl,
      float* __restrict__ Cf)
{
    constexpr int BM = 128, BN = 128;
    constexpr int APL = BM * 80;              // 10240 per plane
    constexpr int BPL = BN * 80;
    constexpr int STG = 2 * APL + 2 * BPL;    // 40960

    extern __shared__ __align__(16) char smem[];
    const uint32_t sb = s2u(smem);
    const int t = threadIdx.x, wid = t >> 5, lid = t & 31;
    const int warp_m0 = (wid >> 2) * 64;      // 2 m-groups
    const int warp_n0 = (wid & 3) * 32;       // 4 n-groups
    const int m0 = blockIdx.y * BM, n0 = blockIdx.x * BN;

    float acc[4][4][4];
    #pragma unroll
    for (int i = 0; i < 4; i++)
        #pragma unroll
        for (int j = 0; j < 4; j++)
            #pragma unroll
            for (int q = 0; q < 4; q++) acc[i][j][q] = 0.0f;

    auto load_tile = [&](int st, int c) {
        const int k0 = c << 5;
        const uint32_t sA = sb + st * STG;
        const uint32_t sB = sA + 2 * APL;
        #pragma unroll
        for (int i = t; i < BM * 4; i += 256) {
            const int row = i >> 2, cc = i & 3;
            const size_t go = (size_t)(m0 + row) * EMB + k0 + cc * 8;
            const uint32_t so = sA + row * 80 + cc * 16;
            cpa16(so, Ah + go);
            cpa16(so + APL, Al + go);
        }
        #pragma unroll
        for (int i = t; i < BN * 4; i += 256) {
            const int row = i >> 2, cc = i & 3;
            const size_t go = (size_t)(n0 + row) * EMB + k0 + cc * 8;
            const uint32_t so = sB + row * 80 + cc * 16;
            cpa16(so, Bh + go);
            cpa16(so + BPL, Bl + go);
        }
    };

    const int nt = EMB >> 5;
    load_tile(0, 0);
    CP_COMMIT();

    for (int c = 0; c < nt; ++c) {
        if (c + 1 < nt) { load_tile((c + 1) & 1, c + 1); CP_COMMIT(); CP_WAIT1(); }
        else            { CP_WAIT0(); }
        __syncthreads();

        const uint32_t sA = sb + (c & 1) * STG;
        const uint32_t sB = sA + 2 * APL;
        #pragma unroll
        for (int ks = 0; ks < 2; ++ks) {
            uint32_t ah[4][4], al[4][4];
            #pragma unroll
            for (int mf = 0; mf < 4; ++mf) {
                const uint32_t ad = sA + (warp_m0 + mf * 16 + (lid & 15)) * 80
                                  + (ks * 2 + (lid >> 4)) * 16;
                ldsm4(ad, ah[mf]);
                ldsm4(ad + APL, al[mf]);
            }
            #pragma unroll
            for (int j = 0; j < 2; ++j) {     // 2 x4-pairs cover 32 n
                const uint32_t bd = sB + (warp_n0 + j * 16 + ((lid >> 4) << 3) + (lid & 7)) * 80
                                  + (ks * 2 + ((lid >> 3) & 1)) * 16;
                uint32_t bh4[4], bl4[4];
                ldsm4(bd, bh4);
                ldsm4(bd + BPL, bl4);
                #pragma unroll
                for (int mf = 0; mf < 4; ++mf) {
                    mma16816(acc[mf][2 * j],     ah[mf], bh4[0], bh4[1]);
                    mma16816(acc[mf][2 * j],     ah[mf], bl4[0], bl4[1]);
                    mma16816(acc[mf][2 * j],     al[mf], bh4[0], bh4[1]);
                    mma16816(acc[mf][2 * j + 1], ah[mf], bh4[2], bh4[3]);
                    mma16816(acc[mf][2 * j + 1], ah[mf], bl4[2], bl4[3]);
                    mma16816(acc[mf][2 * j + 1], al[mf], bh4[2], bh4[3]);
                }
            }
        }
        __syncthreads();
    }

    // ---- epilogue ----
    const int qrow = lid >> 2, qcol = (lid & 3) * 2;
    if constexpr (EPIMODE == 0) {
        #pragma unroll
        for (int mf = 0; mf < 4; ++mf)
            #pragma unroll
            for (int h = 0; h < 2; ++h) {
                const int m = m0 + warp_m0 + mf * 16 + qrow + h * 8;
                float* C = Cf + (size_t)m * EMB + n0 + warp_n0 + qcol;
                #pragma unroll
                for (int nf = 0; nf < 4; ++nf) {
                    float2 v;
                    v.x = acc[mf][nf][h * 2 + 0];
                    v.y = acc[mf][nf][h * 2 + 1];
                    *(float2*)(C + nf * 8) = v;
                }
            }
    } else {
        const int bx = blockIdx.x;
        __nv_bfloat16* H = (bx < 8) ? g_q : (bx < 16 ? g_k : g_v);
        __nv_bfloat16* L = H + PLANE;
        const int col0 = (n0 & 1023) + warp_n0 + qcol;
        #pragma unroll
        for (int mf = 0; mf < 4; ++mf)
            #pragma unroll
            for (int h = 0; h < 2; ++h) {
                const int m = m0 + warp_m0 + mf * 16 + qrow + h * 8;
                const size_t base = (size_t)m * EMB + col0;
                #pragma unroll
                for (int nf = 0; nf < 4; ++nf) {
                    uint32_t hp, lp;
                    split2(acc[mf][nf][h * 2 + 0], acc[mf][nf][h * 2 + 1], hp, lp);
                    *(uint32_t*)(H + base + nf * 8) = hp;
                    *(uint32_t*)(L + base + nf * 8) = lp;
                }
            }
    }
}

// ---------------- fused flash attention ----------------
__global__ void __launch_bounds__(256, 1)
flash_kernel(const __nv_bfloat16* __restrict__ qp, const __nv_bfloat16* __restrict__ kp,
             const __nv_bfloat16* __restrict__ vp,
             __nv_bfloat16* __restrict__ oh, __nv_bfloat16* __restrict__ ol)
{
    extern __shared__ __align__(16) char smem[];
    const uint32_t sb = s2u(smem);
    const int t = threadIdx.x, wid = t >> 5, lid = t & 31;
    const int z = blockIdx.y, b = z >> 4, h = z & 15;
    const int q0 = blockIdx.x * 128;

    constexpr int KP = 144;
    constexpr int QPL = 128 * KP;
    constexpr int KPL = 128 * KP;
    constexpr int VPL = 128 * KP;
    constexpr int STG0  = 2 * QPL;
    constexpr int SOFFV = 2 * KPL;
    constexpr int SOFFM = SOFFV + 2 * VPL;
    constexpr int STGSZ = SOFFM + 128;

    const size_t SE = (size_t)SEQ * EMB;
    const __nv_bfloat16* Qh = qp + (size_t)b * SE + (size_t)h * DK;
    const __nv_bfloat16* Ql = Qh + PLANE;
    const __nv_bfloat16* Kh = kp + (size_t)b * SE + (size_t)h * DK;
    const __nv_bfloat16* Kl = Kh + PLANE;
    const __nv_bfloat16* Vh = vp + (size_t)b * SE + (size_t)h * DK;
    const __nv_bfloat16* Vl = Vh + PLANE;

    #pragma unroll
    for (int i = t; i < 1024; i += 256) {
        const int row = i >> 3, ch = i & 7;
        const size_t g = (size_t)(q0 + row) * EMB + ch * 8;
        const uint32_t so = sb + row * KP + ch * 16;
        cpa16(so, Qh + g); cpa16(so + QPL, Ql + g);
    }
    auto load_kv = [&](int stage, int c) {
        const int kb = c << 7;
        const uint32_t base = sb + STG0 + stage * STGSZ;
        #pragma unroll
        for (int i = t; i < 1024; i += 256) {
            const int row = i >> 3, ch = i & 7;
            const size_t g = (size_t)(kb + row) * EMB + ch * 8;
            const uint32_t so = base + row * KP + ch * 16;
            cpa16(so, Kh + g);         cpa16(so + KPL, Kl + g);
            cpa16(so + SOFFV, Vh + g); cpa16(so + SOFFV + VPL, Vl + g);
        }
        if (t < 8) cpa16(base + SOFFM + t * 16, g_mask + b * SEQ + kb + t * 16);
    };

    load_kv(0, 0);
    CP_COMMIT();
    CP_WAIT0();
    __syncthreads();

    uint32_t qfh[4][4], qfl[4][4];
    #pragma unroll
    for (int ks = 0; ks < 4; ks++) {
        const uint32_t ad = sb + (wid * 16 + (lid & 15)) * KP + (ks * 2 + (lid >> 4)) * 16;
        ldsm4(ad, qfh[ks]);
        ldsm4(ad + QPL, qfl[ks]);
    }

    float o_[8][4];
    #pragma unroll
    for (int i = 0; i < 8; i++)
        #pragma unroll
        for (int j = 0; j < 4; j++) o_[i][j] = 0.0f;
    float m0 = -1e30f, m1 = -1e30f, l0 = 0.0f, l1 = 0.0f;
    const int tq = lid & 3;

    for (int c = 0; c < 16; ++c) {
        if (c + 1 < 16) { load_kv((c + 1) & 1, c + 1); CP_COMMIT(); CP_WAIT1(); }
        else            { CP_WAIT0(); }
        __syncthreads();
        const uint32_t stg = sb + STG0 + (c & 1) * STGSZ;

        float s_[16][4];
        #pragma unroll
        for (int i = 0; i < 16; i++)
            #pragma unroll
            for (int j = 0; j < 4; j++) s_[i][j] = 0.0f;
        #pragma unroll
        for (int ks = 0; ks < 4; ++ks) {
            #pragma unroll
            for (int j = 0; j < 8; ++j) {
                const uint32_t ad = stg + (j * 16 + ((lid >> 4) << 3) + (lid & 7)) * KP
                                  + (ks * 2 + ((lid >> 3) & 1)) * 16;
                uint32_t kf[4], kfl[4];
                ldsm4(ad, kf); ldsm4(ad + KPL, kfl);
                mma16816(s_[2 * j],     qfh[ks], kf[0],  kf[1]);
                mma16816(s_[2 * j],     qfh[ks], kfl[0], kfl[1]);
                mma16816(s_[2 * j],     qfl[ks], kf[0],  kf[1]);
                mma16816(s_[2 * j + 1], qfh[ks], kf[2],  kf[3]);
                mma16816(s_[2 * j + 1], qfh[ks], kfl[2], kfl[3]);
                mma16816(s_[2 * j + 1], qfl[ks], kf[2],  kf[3]);
            }
        }

        const unsigned char* mptr = (const unsigned char*)smem + STG0 + (c & 1) * STGSZ + SOFFM;
        float tmx0 = -1e30f, tmx1 = -1e30f;
        #pragma unroll
        for (int nf = 0; nf < 16; ++nf) {
            const uchar2 mk = *(const uchar2*)(mptr + nf * 8 + 2 * tq);
            const float v0 = mk.x ? -1e9f : 0.125f * s_[nf][0];
            const float v1 = mk.y ? -1e9f : 0.125f * s_[nf][1];
            const float v2 = mk.x ? -1e9f : 0.125f * s_[nf][2];
            const float v3 = mk.y ? -1e9f : 0.125f * s_[nf][3];
            s_[nf][0] = v0; s_[nf][1] = v1; s_[nf][2] = v2; s_[nf][3] = v3;
            tmx0 = fmaxf(tmx0, fmaxf(v0, v1));
            tmx1 = fmaxf(tmx1, fmaxf(v2, v3));
        }
        tmx0 = fmaxf(tmx0, __shfl_xor_sync(0xffffffffu, tmx0, 1));
        tmx0 = fmaxf(tmx0, __shfl_xor_sync(0xffffffffu, tmx0, 2));
        tmx1 = fmaxf(tmx1, __shfl_xor_sync(0xffffffffu, tmx1, 1));
        tmx1 = fmaxf(tmx1, __shfl_xor_sync(0xffffffffu, tmx1, 2));
        const float mn0 = fmaxf(m0, tmx0), mn1 = fmaxf(m1, tmx1);
        const float a0 = __expf(m0 - mn0), a1 = __expf(m1 - mn1);
        m0 = mn0; m1 = mn1;
        float sum0 = 0.0f, sum1 = 0.0f;
        #pragma unroll
        for (int nf = 0; nf < 16; ++nf) {
            const float p0 = __expf(s_[nf][0] - m0);
            const float p1 = __expf(s_[nf][1] - m0);
            const float p2 = __expf(s_[nf][2] - m1);
            const float p3 = __expf(s_[nf][3] - m1);
            s_[nf][0] = p0; s_[nf][1] = p1; s_[nf][2] = p2; s_[nf][3] = p3;
            sum0 += p0 + p1; sum1 += p2 + p3;
        }
        sum0 += __shfl_xor_sync(0xffffffffu, sum0, 1);
        sum0 += __shfl_xor_sync(0xffffffffu, sum0, 2);
        sum1 += __shfl_xor_sync(0xffffffffu, sum1, 1);
        sum1 += __shfl_xor_sync(0xffffffffu, sum1, 2);
        l0 = l0 * a0 + sum0;
        l1 = l1 * a1 + sum1;
        #pragma unroll
        for (int nf = 0; nf < 8; ++nf) {
            o_[nf][0] *= a0; o_[nf][1] *= a0;
            o_[nf][2] *= a1; o_[nf][3] *= a1;
        }

        #pragma unroll
        for (int ks = 0; ks < 8; ++ks) {
            uint32_t ph4[4], pl4[4];
            split2(s_[2 * ks][0],     s_[2 * ks][1],     ph4[0], pl4[0]);
            split2(s_[2 * ks][2],     s_[2 * ks][3],     ph4[1], pl4[1]);
            split2(s_[2 * ks + 1][0], s_[2 * ks + 1][1], ph4[2], pl4[2]);
            split2(s_[2 * ks + 1][2], s_[2 * ks + 1][3], ph4[3], pl4[3]);
            #pragma unroll
            for (int j = 0; j < 4; ++j) {
                const uint32_t ad = stg + SOFFV
                                  + (ks * 16 + (((lid >> 3) & 1) << 3) + (lid & 7)) * KP
                                  + (j * 16 + ((lid >> 4) << 3)) * 2;
                uint32_t vf[4], vfl[4];
                ldsm4t(ad, vf); ldsm4t(ad + VPL, vfl);
                mma16816(o_[2 * j],     ph4, vf[0],  vf[1]);
                mma16816(o_[2 * j],     ph4, vfl[0], vfl[1]);
                mma16816(o_[2 * j],     pl4, vf[0],  vf[1]);
                mma16816(o_[2 * j + 1], ph4, vf[2],  vf[3]);
                mma16816(o_[2 * j + 1], ph4, vfl[2], vfl[3]);
                mma16816(o_[2 * j + 1], pl4, vf[2],  vf[3]);
            }
        }
        __syncthreads();
    }

    const float inv0 = 1.0f / l0, inv1 = 1.0f / l1;
    const int g = lid >> 2;
    const size_t r0 = (size_t)(b * SEQ + q0 + wid * 16 + g) * EMB + h * DK + 2 * tq;
    const size_t r1 = r0 + (size_t)8 * EMB;
    #pragma unroll
    for (int nf = 0; nf < 8; ++nf) {
        uint32_t hi0, lo0, hi1, lo1;
        split2(o_[nf][0] * inv0, o_[nf][1] * inv0, hi0, lo0);
        split2(o_[nf][2] * inv1, o_[nf][3] * inv1, hi1, lo1);
        *(uint32_t*)(oh + r0 + nf * 8) = hi0;
        *(uint32_t*)(ol + r0 + nf * 8) = lo0;
        *(uint32_t*)(oh + r1 + nf * 8) = hi1;
        *(uint32_t*)(ol + r1 + nf * 8) = lo1;
    }
}

// ---------------- launch ----------------
// Launch order chosen so ncu's "-s 5 -c 1" capture lands on flash_kernel:
//   1 mask, 2 split-x, 3 split3(wq,wk,wv), 4 QKV, 5 split-wo, 6 FLASH, 7 final.
extern "C" void kernel_launch(void* const* d_in, const int* in_sizes, int n_in,
                              void* d_out, int out_size)
{
    const float* x  = (const float*)d_in[0];
    const void*  mk = d_in[1];
    const float* wq = (const float*)d_in[2];
    const float* wk = (const float*)d_in[3];
    const float* wv = (const float*)d_in[4];
    const float* wo = (const float*)d_in[5];
    float* out = (float*)d_out;

    __nv_bfloat16 *xh, *xl, *wh, *wl, *qp, *kp, *vpp, *ath, *atl;
    cudaGetSymbolAddress((void**)&xh,  g_x_hi);
    cudaGetSymbolAddress((void**)&xl,  g_x_lo);
    cudaGetSymbolAddress((void**)&wh,  g_w_hi);
    cudaGetSymbolAddress((void**)&wl,  g_w_lo);
    cudaGetSymbolAddress((void**)&qp,  g_q);
    cudaGetSymbolAddress((void**)&kp,  g_k);
    cudaGetSymbolAddress((void**)&vpp, g_v);
    cudaGetSymbolAddress((void**)&ath, g_at_hi);
    cudaGetSymbolAddress((void**)&atl, g_at_lo);

    const int SM128   = 2 * (2 * 128 * 80 + 2 * 128 * 80);   // 81920 -> 2 CTAs/SM
    const int SMFLASH = 2 * 128 * 144 + 2 * 73856;           // 184576
    cudaFuncSetAttribute(mm128<0>, cudaFuncAttributeMaxDynamicSharedMemorySize, SM128);
    cudaFuncSetAttribute(mm128<3>, cudaFuncAttributeMaxDynamicSharedMemorySize, SM128);
    cudaFuncSetAttribute(flash_kernel, cudaFuncAttributeMaxDynamicSharedMemorySize, SMFLASH);

    const int NX4 = (MTOK * EMB) / 4, NW4 = (EMB * EMB) / 4;
    const size_t WSZ = (size_t)EMB * EMB;

    // 1) mask
    mask_canon_kernel<<<1, 256>>>(mk);
    // 2) x split
    split_kernel<<<(NX4 + 255) / 256, 256>>>(x, xh, xl, NX4);
    // 3) wq/wk/wv splits fused
    split3_kernel<<<3 * 1024, 256>>>(wq, wk, wv);
    // 4) merged QKV projection (768 CTAs, 2 CTAs/SM)
    const dim3 gqkv(24, 32);
    mm128<3><<<gqkv, 256, SM128>>>(xh, xl, wh, wl, nullptr);
    // 5) wo split (only needed by step 7)
    split_kernel<<<(NW4 + 255) / 256, 256>>>(wo, wh + 3 * WSZ, wl + 3 * WSZ, NW4);
    // 6) fused attention  <-- ncu capture target
    const dim3 gflash(SEQ / 128, ZBH);
    flash_kernel<<<gflash, 256, SMFLASH>>>(qp, kp, vpp, ath, atl);
    // 7) final projection (256 CTAs, single wave at 2 CTAs/SM)
    const dim3 gfin(8, 32);
    mm128<0><<<gfin, 256, SM128>>>(ath, atl, wh + 3 * WSZ, wl + 3 * WSZ, out);
}